// round 4
// baseline (speedup 1.0000x reference)
#include <cuda_runtime.h>
#include <cuda_bf16.h>

// RocketConv: 84 ternary dilated kernels; y = -S + 3*(tap_a+tap_b+tap_c).
// Output plane index within batch: idx = c*84 + k (reshape is reinterpretation).
//
// R4: 8 t per thread (two float4 stores per plane), block=128, grid=1024.
// Total threads 131072 <= resident (148 SMs x 7 CTAs x 128 thr = 132608)
// => single wave, longer per-thread write bursts, fewer concurrent streams.

#define T_LEN 4096
#define C_LEN 16
#define NK 84

__global__ __launch_bounds__(128, 7) void rocketconv_kernel(
    const float* __restrict__ x, float* __restrict__ out)
{
    // 1024 blocks: row = b*16+c (0..255), tile = quarter of T (1024 t each)
    const int row  = blockIdx.x >> 2;
    const int tile = blockIdx.x & 3;
    const int t0   = tile * 1024 + threadIdx.x * 8;   // 8 t per thread

    const float* __restrict__ xr = x + row * T_LEN;

    // v[i] = x[t0 - 16 + i], i in [0,40): tap j for lane q (0..7) is v[q + 4*j]
    float v[40];
#pragma unroll
    for (int i = 0; i < 10; i++) {
        const int t = t0 - 16 + i * 4;
        if (t >= 0 && t + 3 < T_LEN) {
            const float4 f = *reinterpret_cast<const float4*>(xr + t);
            v[i * 4 + 0] = f.x; v[i * 4 + 1] = f.y;
            v[i * 4 + 2] = f.z; v[i * 4 + 3] = f.w;
        } else {
#pragma unroll
            for (int q = 0; q < 4; q++) {
                const int tt = t + q;
                v[i * 4 + q] = (tt >= 0 && tt < T_LEN) ? xr[tt] : 0.0f;
            }
        }
    }

    // -S per lane (S = sum of the 9 taps)
    float nS[8];
#pragma unroll
    for (int q = 0; q < 8; q++) {
        float s = 0.0f;
#pragma unroll
        for (int j = 0; j < 9; j++) s += v[q + 4 * j];
        nS[q] = -s;
    }

    // out base: plane idx = c*84 inside batch b; row = b*16+c
    const int b = row >> 4;
    const int c = row & 15;
    float* __restrict__ o =
        out + ((size_t)b * NK * C_LEN + (size_t)c * NK) * T_LEN + t0;

    // 84 kernels, fully unrolled (compile-time tap indices -> registers)
#pragma unroll
    for (int a = 0; a < 9; a++) {
#pragma unroll
        for (int bb = a + 1; bb < 9; bb++) {
#pragma unroll
            for (int cc = bb + 1; cc < 9; cc++) {
                float4 r0, r1;
                r0.x = fmaf(3.0f, v[0 + 4*a] + v[0 + 4*bb] + v[0 + 4*cc], nS[0]);
                r0.y = fmaf(3.0f, v[1 + 4*a] + v[1 + 4*bb] + v[1 + 4*cc], nS[1]);
                r0.z = fmaf(3.0f, v[2 + 4*a] + v[2 + 4*bb] + v[2 + 4*cc], nS[2]);
                r0.w = fmaf(3.0f, v[3 + 4*a] + v[3 + 4*bb] + v[3 + 4*cc], nS[3]);
                r1.x = fmaf(3.0f, v[4 + 4*a] + v[4 + 4*bb] + v[4 + 4*cc], nS[4]);
                r1.y = fmaf(3.0f, v[5 + 4*a] + v[5 + 4*bb] + v[5 + 4*cc], nS[5]);
                r1.z = fmaf(3.0f, v[6 + 4*a] + v[6 + 4*bb] + v[6 + 4*cc], nS[6]);
                r1.w = fmaf(3.0f, v[7 + 4*a] + v[7 + 4*bb] + v[7 + 4*cc], nS[7]);
                *reinterpret_cast<float4*>(o)     = r0;
                *reinterpret_cast<float4*>(o + 4) = r1;
                o += T_LEN;  // next kernel plane (contiguous within (b,c))
            }
        }
    }
}

extern "C" void kernel_launch(void* const* d_in, const int* in_sizes, int n_in,
                              void* d_out, int out_size)
{
    const float* x = (const float*)d_in[0];
    float* out = (float*)d_out;
    // 256 rows (B*C) * 4 tiles per row = 1024 blocks of 128 threads (8 t/thread)
    rocketconv_kernel<<<1024, 128>>>(x, out);
}

// round 5
// speedup vs baseline: 3.3822x; 3.3822x over previous
#include <cuda_runtime.h>
#include <cuda_bf16.h>

// RocketConv: 84 ternary dilated kernels; y = -S + 3*(tap_a+tap_b+tap_c).
// Output plane index within batch: idx = c*84 + k (reshape is reinterpretation).
//
// R5: revert to R2's verified store pattern (4 t/thread, one float4 per plane,
// warp store = 512 B fully contiguous / full sectors). Change ONLY grid
// granularity: 2048 CTAs x 128 threads (512-t tiles) so the final partial
// wave is twice as fine-grained -> smaller straggler tail.

#define T_LEN 4096
#define C_LEN 16
#define NK 84

__global__ __launch_bounds__(128) void rocketconv_kernel(
    const float* __restrict__ x, float* __restrict__ out)
{
    // blockIdx.x in [0, 2048): row = b*16+c (0..255), tile = eighth of T
    const int row  = blockIdx.x >> 3;
    const int tile = blockIdx.x & 7;
    const int t0   = tile * 512 + threadIdx.x * 4;

    const float* __restrict__ xr = x + row * T_LEN;

    // v[i] = x[t0 - 16 + i], i in [0,36): tap j for lane q is v[q + 4*j]
    float v[36];
#pragma unroll
    for (int i = 0; i < 9; i++) {
        const int t = t0 - 16 + i * 4;
        if (t >= 0 && t + 3 < T_LEN) {
            const float4 f = *reinterpret_cast<const float4*>(xr + t);
            v[i * 4 + 0] = f.x; v[i * 4 + 1] = f.y;
            v[i * 4 + 2] = f.z; v[i * 4 + 3] = f.w;
        } else {
#pragma unroll
            for (int q = 0; q < 4; q++) {
                const int tt = t + q;
                v[i * 4 + q] = (tt >= 0 && tt < T_LEN) ? xr[tt] : 0.0f;
            }
        }
    }

    // -S per lane (S = sum of 9 taps)
    float nS[4];
#pragma unroll
    for (int q = 0; q < 4; q++) {
        float s = 0.0f;
#pragma unroll
        for (int j = 0; j < 9; j++) s += v[q + 4 * j];
        nS[q] = -s;
    }

    // out base: plane idx = c*84 inside batch b; row = b*16+c
    const int b = row >> 4;
    const int c = row & 15;
    float* __restrict__ o =
        out + ((size_t)b * NK * C_LEN + (size_t)c * NK) * T_LEN + t0;

    // 84 kernels in lexicographic combination order, fully unrolled
#pragma unroll
    for (int a = 0; a < 9; a++) {
#pragma unroll
        for (int bb = a + 1; bb < 9; bb++) {
#pragma unroll
            for (int cc = bb + 1; cc < 9; cc++) {
                float4 r;
                r.x = fmaf(3.0f, v[0 + 4*a] + v[0 + 4*bb] + v[0 + 4*cc], nS[0]);
                r.y = fmaf(3.0f, v[1 + 4*a] + v[1 + 4*bb] + v[1 + 4*cc], nS[1]);
                r.z = fmaf(3.0f, v[2 + 4*a] + v[2 + 4*bb] + v[2 + 4*cc], nS[2]);
                r.w = fmaf(3.0f, v[3 + 4*a] + v[3 + 4*bb] + v[3 + 4*cc], nS[3]);
                *reinterpret_cast<float4*>(o) = r;
                o += T_LEN;  // next kernel plane (contiguous within (b,c))
            }
        }
    }
}

extern "C" void kernel_launch(void* const* d_in, const int* in_sizes, int n_in,
                              void* d_out, int out_size)
{
    const float* x = (const float*)d_in[0];
    float* out = (float*)d_out;
    // 256 rows (B*C) * 8 tiles per row = 2048 blocks of 128 threads (4 t/thread)
    rocketconv_kernel<<<2048, 128>>>(x, out);
}

// round 6
// speedup vs baseline: 3.5995x; 1.0643x over previous
#include <cuda_runtime.h>
#include <cuda_bf16.h>

// RocketConv: 84 ternary dilated kernels; y = -S + 3*(tap_a+tap_b+tap_c).
// Output plane index within batch: idx = c*84 + k (reshape is reinterpretation).
//
// R6: identical kernel body to R2 (best store pattern: 4 t/thread, one
// float4 per plane, warp burst 512B fully contiguous). Single change:
// reserve 76KB dynamic smem per CTA to cap residency at 2 CTAs/SM
// (296 concurrent write streams instead of 592) to improve DRAM
// row-buffer locality of the 16KB-strided plane walk.

#define T_LEN 4096
#define C_LEN 16
#define NK 84

extern __shared__ float smem_unused[];  // occupancy limiter only

__global__ __launch_bounds__(256) void rocketconv_kernel(
    const float* __restrict__ x, float* __restrict__ out)
{
    // blockIdx.x in [0, 1024): row = b*16+c (0..255), tile = quarter of T
    const int row  = blockIdx.x >> 2;
    const int tile = blockIdx.x & 3;
    const int t0   = tile * 1024 + threadIdx.x * 4;

    const float* __restrict__ xr = x + row * T_LEN;

    // v[i] = x[t0 - 16 + i], i in [0,36): tap j for lane q is v[q + 4*j]
    float v[36];
#pragma unroll
    for (int i = 0; i < 9; i++) {
        const int t = t0 - 16 + i * 4;
        if (t >= 0 && t + 3 < T_LEN) {
            const float4 f = *reinterpret_cast<const float4*>(xr + t);
            v[i * 4 + 0] = f.x; v[i * 4 + 1] = f.y;
            v[i * 4 + 2] = f.z; v[i * 4 + 3] = f.w;
        } else {
#pragma unroll
            for (int q = 0; q < 4; q++) {
                const int tt = t + q;
                v[i * 4 + q] = (tt >= 0 && tt < T_LEN) ? xr[tt] : 0.0f;
            }
        }
    }

    // -S per lane (S = sum of 9 taps)
    float nS[4];
#pragma unroll
    for (int q = 0; q < 4; q++) {
        float s = 0.0f;
#pragma unroll
        for (int j = 0; j < 9; j++) s += v[q + 4 * j];
        nS[q] = -s;
    }

    // out base: plane idx = c*84 inside batch b; row = b*16+c
    const int b = row >> 4;
    const int c = row & 15;
    float* __restrict__ o =
        out + ((size_t)b * NK * C_LEN + (size_t)c * NK) * T_LEN + t0;

    // 84 kernels in lexicographic combination order, fully unrolled
#pragma unroll
    for (int a = 0; a < 9; a++) {
#pragma unroll
        for (int bb = a + 1; bb < 9; bb++) {
#pragma unroll
            for (int cc = bb + 1; cc < 9; cc++) {
                float4 r;
                r.x = fmaf(3.0f, v[0 + 4*a] + v[0 + 4*bb] + v[0 + 4*cc], nS[0]);
                r.y = fmaf(3.0f, v[1 + 4*a] + v[1 + 4*bb] + v[1 + 4*cc], nS[1]);
                r.z = fmaf(3.0f, v[2 + 4*a] + v[2 + 4*bb] + v[2 + 4*cc], nS[2]);
                r.w = fmaf(3.0f, v[3 + 4*a] + v[3 + 4*bb] + v[3 + 4*cc], nS[3]);
                *reinterpret_cast<float4*>(o) = r;
                o += T_LEN;  // next kernel plane (contiguous within (b,c))
            }
        }
    }
}

extern "C" void kernel_launch(void* const* d_in, const int* in_sizes, int n_in,
                              void* d_out, int out_size)
{
    const float* x = (const float*)d_in[0];
    float* out = (float*)d_out;

    // Allow >48KB dynamic smem; idempotent + deterministic every call.
    cudaFuncSetAttribute(rocketconv_kernel,
                         cudaFuncAttributeMaxDynamicSharedMemorySize,
                         76 * 1024);

    // 256 rows (B*C) * 4 tiles = 1024 blocks of 256 threads; 76KB smem
    // reservation caps residency at 2 CTAs/SM.
    rocketconv_kernel<<<1024, 256, 76 * 1024>>>(x, out);
}